// round 3
// baseline (speedup 1.0000x reference)
#include <cuda_runtime.h>
#include <cuda_bf16.h>
#include <cstdint>

// Problem constants
#define BB 8
#define HH 768
#define LL 4096
#define N2 4096          // complex FFT size (= N/2, N = 8192)
#define LOGN2 12
#define KF_STRIDE 4100   // 4097 used, padded

#define PI_F 3.14159265358979323846f

// Scratch (device globals: allocation APIs are forbidden)
__device__ float  g_y[(size_t)BB * HH * LL];          // gelu(conv+skip), ~100.7 MB
__device__ float2 g_kf[(size_t)HH * KF_STRIDE];       // kernel spectrum, ~25 MB

// ---------------------------------------------------------------------------
// complex helpers
__device__ __forceinline__ float2 cmul(float2 a, float2 b) {
    return make_float2(a.x * b.x - a.y * b.y, a.x * b.y + a.y * b.x);
}
__device__ __forceinline__ float2 cmulc(float2 a, float2 b) {  // a * conj(b)
    return make_float2(a.x * b.x + a.y * b.y, a.y * b.x - a.x * b.y);
}

__device__ __forceinline__ float gelu_exact(float x) {
    return 0.5f * x * (1.0f + erff(x * 0.70710678118654752f));
}

// ---------------------------------------------------------------------------
// Stockham radix-2 FFT of 4096 complex points in shared memory.
// 512 threads, 12 stages, ping-pong bufA <-> bufB, result ends in bufA.
// tw[i] = exp(-2*pi*i*i/4096) for i in [0,2048). INV=true flips twiddle sign.
template <bool INV>
__device__ void fft4096(float2* bufA, float2* bufB, const float2* tw, int tid) {
    float2* src = bufA;
    float2* dst = bufB;
#pragma unroll 1
    for (int stage = 0; stage < LOGN2; ++stage) {
        __syncthreads();
        const int s = 1 << stage;
#pragma unroll
        for (int it = 0; it < 4; ++it) {
            int i = tid + it * 512;          // 0..2047  (i = p*s + q)
            int p = i >> stage;
            int q = i & (s - 1);
            float2 w = tw[p << stage];
            if (INV) w.y = -w.y;
            float2 a  = src[i];              // q + s*p == i
            float2 b  = src[i + 2048];       // q + s*(p+m)
            float2 sum = make_float2(a.x + b.x, a.y + b.y);
            float2 dif = make_float2(a.x - b.x, a.y - b.y);
            int od = q + s * 2 * p;
            dst[od]     = sum;
            dst[od + s] = cmul(dif, w);
        }
        float2* t = src; src = dst; dst = t;
    }
    __syncthreads();
}

__device__ __forceinline__ void build_twiddles(float2* tw, int tid) {
    for (int i = tid; i < 2048; i += 512) {
        float s, c;
        __sincosf(-(2.0f * PI_F / (float)N2) * (float)i, &s, &c);
        tw[i] = make_float2(c, s);
    }
}

// ---------------------------------------------------------------------------
// Kernel 1: spectrum of conv kernel k (768 rows).
// Real FFT of length 8192 (input length 4096, zero-padded) via complex 4096.
__global__ void kf_kernel(const float* __restrict__ kin) {
    extern __shared__ float2 sm[];
    float2* A  = sm;
    float2* Bb = sm + N2;
    float2* tw = sm + 2 * N2;
    const int h   = blockIdx.x;
    const int tid = threadIdx.x;

    build_twiddles(tw, tid);

    const float2* kr = (const float2*)(kin + (size_t)h * LL);
#pragma unroll
    for (int it = 0; it < 4; ++it) {
        int n = tid + it * 512;   // 0..2047 -> data
        A[n] = kr[n];
    }
#pragma unroll
    for (int it = 4; it < 8; ++it) {
        int n = tid + it * 512;   // 2048..4095 -> zero pad
        A[n] = make_float2(0.f, 0.f);
    }

    fft4096<false>(A, Bb, tw, tid);

    float2* kf = g_kf + (size_t)h * KF_STRIDE;
    for (int k = tid; k <= 2048; k += 512) {
        if (k == 0) {
            float2 Z0 = A[0];
            kf[0]    = make_float2(Z0.x + Z0.y, 0.f);   // X[0]
            kf[4096] = make_float2(Z0.x - Z0.y, 0.f);   // X[N/2]
        } else if (k == 2048) {
            float2 Z = A[2048];
            kf[2048] = make_float2(Z.x, -Z.y);          // conj(Z)
        } else {
            int kp = N2 - k;
            float2 Zk = A[k], Zp = A[kp];
            float2 Fe = make_float2(0.5f * (Zk.x + Zp.x), 0.5f * (Zk.y - Zp.y));
            float2 Fo = make_float2(0.5f * (Zk.y + Zp.y), 0.5f * (Zp.x - Zk.x));
            float sw, cw;
            __sincosf(-(2.0f * PI_F / 8192.0f) * (float)k, &sw, &cw);
            float2 W = make_float2(cw, sw);
            float2 t = cmul(Fo, W);
            kf[k]  = make_float2(Fe.x + t.x, Fe.y + t.y);        // X[k]
            kf[kp] = make_float2(Fe.x - t.x, -(Fe.y - t.y));     // conj(Fe - W*Fo)
        }
    }
}

// ---------------------------------------------------------------------------
// Kernel 2: per (b,h) row — rfft(u) * Kf -> irfft -> + D*u -> gelu -> g_y
__global__ void conv_kernel(const float* __restrict__ u, const float* __restrict__ D) {
    extern __shared__ float2 sm[];
    float2* A  = sm;
    float2* Bb = sm + N2;
    float2* tw = sm + 2 * N2;
    const int row = blockIdx.x;          // b*HH + h
    const int tid = threadIdx.x;
    const int hh  = row % HH;

    build_twiddles(tw, tid);

    const float2* u2 = (const float2*)(u + (size_t)row * LL);
    float2 ureg[4];
#pragma unroll
    for (int it = 0; it < 4; ++it) {
        int n = tid + it * 512;
        float2 v = u2[n];
        ureg[it] = v;
        A[n] = v;
    }
#pragma unroll
    for (int it = 4; it < 8; ++it) {
        int n = tid + it * 512;
        A[n] = make_float2(0.f, 0.f);
    }

    fft4096<false>(A, Bb, tw, tid);   // Z in A

    // fused: untangle (Z -> X), spectral multiply by Kf, repack (Y -> Z2), in place
    const float2* kf = g_kf + (size_t)hh * KF_STRIDE;
    for (int k = tid; k <= 2048; k += 512) {
        if (k == 0) {
            float2 Z0 = A[0];
            float X0 = Z0.x + Z0.y;      // X[0]   (real)
            float X1 = Z0.x - Z0.y;      // X[N/2] (real)
            float2 K0 = kf[0], K1 = kf[4096];
            float2 Y0 = make_float2(X0 * K0.x, X0 * K0.y);
            float2 Y1 = make_float2(X1 * K1.x, X1 * K1.y);
            float2 Ge = make_float2(0.5f * (Y0.x + Y1.x), 0.5f * (Y0.y - Y1.y));
            float2 Go = make_float2(0.5f * (Y0.x - Y1.x), 0.5f * (Y0.y + Y1.y));
            A[0] = make_float2(Ge.x - Go.y, Ge.y + Go.x);
        } else if (k == 2048) {
            float2 Z = A[2048];
            float2 X = make_float2(Z.x, -Z.y);
            float2 Y = cmul(X, kf[2048]);
            A[2048] = make_float2(Y.x, -Y.y);
        } else {
            int kp = N2 - k;
            float2 Zk = A[k], Zp = A[kp];
            float2 Fe = make_float2(0.5f * (Zk.x + Zp.x), 0.5f * (Zk.y - Zp.y));
            float2 Fo = make_float2(0.5f * (Zk.y + Zp.y), 0.5f * (Zp.x - Zk.x));
            float sw, cw;
            __sincosf(-(2.0f * PI_F / 8192.0f) * (float)k, &sw, &cw);
            float2 W = make_float2(cw, sw);
            float2 t = cmul(Fo, W);
            float2 Xk = make_float2(Fe.x + t.x, Fe.y + t.y);
            float2 Xp = make_float2(Fe.x - t.x, -(Fe.y - t.y));
            float2 Ya = cmul(Xk, kf[k]);
            float2 Yb = cmul(Xp, kf[kp]);
            float2 Ge = make_float2(0.5f * (Ya.x + Yb.x), 0.5f * (Ya.y - Yb.y));
            float2 Am = make_float2(0.5f * (Ya.x - Yb.x), 0.5f * (Ya.y + Yb.y));
            float2 Go = cmulc(Am, W);   // * exp(+2*pi*i*k/8192)
            A[k]  = make_float2(Ge.x - Go.y, Ge.y + Go.x);
            A[kp] = make_float2(Ge.x + Go.y, Go.x - Ge.y);
        }
    }

    fft4096<true>(A, Bb, tw, tid);    // z2 in A (unscaled inverse)

    const float Dh  = D[hh];
    const float inv = 1.0f / (float)N2;
    float* yout = g_y + (size_t)row * LL;
#pragma unroll
    for (int it = 0; it < 4; ++it) {
        int n = tid + it * 512;
        float2 z = A[n];
        float y0 = z.x * inv + Dh * ureg[it].x;
        float y1 = z.y * inv + Dh * ureg[it].y;
        yout[2 * n]     = gelu_exact(y0);
        yout[2 * n + 1] = gelu_exact(y1);
    }
}

// ---------------------------------------------------------------------------
// Kernel 3: per-batch GEMM  Z = W(1536x768) @ Y(768x4096), + bias, GLU fused.
// Tile: 128 W-rows (64 "a" rows h0..h0+63 paired with 64 "g" rows 768+h0..)
//       x 128 L-cols. 256 threads, 8x8 micro-tile (4 a-rows + 4 g-rows x 8 cols).
#define BKK 16
__global__ __launch_bounds__(256) void gemm_glu_kernel(
    const float* __restrict__ W, const float* __restrict__ bias,
    float* __restrict__ out) {
    __shared__ __align__(16) float Ws[BKK][128];
    __shared__ __align__(16) float Ys[BKK][128];

    const int b  = blockIdx.z;
    const int h0 = blockIdx.y * 64;
    const int l0 = blockIdx.x * 128;
    const int t  = threadIdx.x;
    const int ty = t >> 4;       // 0..15 -> 4 paired rows each
    const int tx = t & 15;       // 0..15 -> 8 cols each

    float acc_a[4][8];
    float acc_g[4][8];
#pragma unroll
    for (int j = 0; j < 4; ++j)
#pragma unroll
        for (int c = 0; c < 8; ++c) { acc_a[j][c] = 0.f; acc_g[j][c] = 0.f; }

    const float* Yb = g_y + (size_t)b * HH * LL;

    // W loader mapping: r = t & 127 (smem store conflict-free), kc = (t>>7)*8
    const int wr  = t & 127;
    const int wkc = (t >> 7) * 8;
    const int wo  = (wr < 64) ? (h0 + wr) : (HH + h0 + wr - 64);
    const float* wbase = W + (size_t)wo * HH + wkc;

    // Y loader mapping: kk = t >> 4, lc = (t&15)*8
    const int ykk = t >> 4;
    const int ylc = (t & 15) * 8;

    for (int k0 = 0; k0 < HH; k0 += BKK) {
        __syncthreads();
        {
            const float* wp = wbase + k0;
            float4 w0 = *(const float4*)wp;
            float4 w1 = *(const float4*)(wp + 4);
            Ws[wkc + 0][wr] = w0.x; Ws[wkc + 1][wr] = w0.y;
            Ws[wkc + 2][wr] = w0.z; Ws[wkc + 3][wr] = w0.w;
            Ws[wkc + 4][wr] = w1.x; Ws[wkc + 5][wr] = w1.y;
            Ws[wkc + 6][wr] = w1.z; Ws[wkc + 7][wr] = w1.w;
        }
        {
            const float* yp = Yb + (size_t)(k0 + ykk) * LL + l0 + ylc;
            float4 y0 = *(const float4*)yp;
            float4 y1 = *(const float4*)(yp + 4);
            *(float4*)&Ys[ykk][ylc]     = y0;
            *(float4*)&Ys[ykk][ylc + 4] = y1;
        }
        __syncthreads();

#pragma unroll
        for (int kk = 0; kk < BKK; ++kk) {
            float4 wa = *(const float4*)&Ws[kk][ty * 4];
            float4 wg = *(const float4*)&Ws[kk][64 + ty * 4];
            float4 y0 = *(const float4*)&Ys[kk][tx * 8];
            float4 y1 = *(const float4*)&Ys[kk][tx * 8 + 4];
            float yv[8] = {y0.x, y0.y, y0.z, y0.w, y1.x, y1.y, y1.z, y1.w};
            float wav[4] = {wa.x, wa.y, wa.z, wa.w};
            float wgv[4] = {wg.x, wg.y, wg.z, wg.w};
#pragma unroll
            for (int j = 0; j < 4; ++j)
#pragma unroll
                for (int c = 0; c < 8; ++c) {
                    acc_a[j][c] = fmaf(wav[j], yv[c], acc_a[j][c]);
                    acc_g[j][c] = fmaf(wgv[j], yv[c], acc_g[j][c]);
                }
        }
    }

    // Epilogue: GLU  out = (za) * sigmoid(zg)
#pragma unroll
    for (int j = 0; j < 4; ++j) {
        const int hrow = h0 + ty * 4 + j;
        const float ba = bias[hrow];
        const float bg = bias[HH + hrow];
        float* op = out + ((size_t)b * HH + hrow) * LL + l0 + tx * 8;
        float res[8];
#pragma unroll
        for (int c = 0; c < 8; ++c) {
            float za = acc_a[j][c] + ba;
            float zg = acc_g[j][c] + bg;
            res[c] = za / (1.0f + __expf(-zg));
        }
        *(float4*)op       = make_float4(res[0], res[1], res[2], res[3]);
        *(float4*)(op + 4) = make_float4(res[4], res[5], res[6], res[7]);
    }
}

// ---------------------------------------------------------------------------
extern "C" void kernel_launch(void* const* d_in, const int* in_sizes, int n_in,
                              void* d_out, int out_size) {
    const float* u  = (const float*)d_in[0];   // (B, H, L)
    const float* k  = (const float*)d_in[1];   // (1, H, L)
    const float* D  = (const float*)d_in[2];   // (1, H)
    const float* W  = (const float*)d_in[3];   // (2H, H)
    const float* bv = (const float*)d_in[4];   // (2H,)
    float* out = (float*)d_out;

    const int smem_fft = (N2 * 2 + 2048) * sizeof(float2);   // 80 KB
    cudaFuncSetAttribute(kf_kernel,   cudaFuncAttributeMaxDynamicSharedMemorySize, smem_fft);
    cudaFuncSetAttribute(conv_kernel, cudaFuncAttributeMaxDynamicSharedMemorySize, smem_fft);

    kf_kernel<<<HH, 512, smem_fft>>>(k);
    conv_kernel<<<BB * HH, 512, smem_fft>>>(u, D);
    gemm_glu_kernel<<<dim3(LL / 128, HH / 64, BB), 256>>>(W, bv, out);
}

// round 4
// speedup vs baseline: 1.0003x; 1.0003x over previous
#include <cuda_runtime.h>
#include <cuda_bf16.h>
#include <cstdint>

// Problem constants
#define BB 8
#define HH 768
#define LL 4096
#define N2 4096          // complex FFT size (= N/2, N = 8192)
#define LOGN2 12
#define KF_STRIDE 4100   // 4097 used, padded

#define PI_F 3.14159265358979323846f

// Scratch (device globals: allocation APIs are forbidden)
__device__ float  g_y[(size_t)BB * HH * LL];          // gelu(conv+skip), ~100.7 MB
__device__ float2 g_kf[(size_t)HH * KF_STRIDE];       // kernel spectrum, ~25 MB

// ---------------------------------------------------------------------------
// complex helpers
__device__ __forceinline__ float2 cmul(float2 a, float2 b) {
    return make_float2(a.x * b.x - a.y * b.y, a.x * b.y + a.y * b.x);
}
__device__ __forceinline__ float2 cmulc(float2 a, float2 b) {  // a * conj(b)
    return make_float2(a.x * b.x + a.y * b.y, a.y * b.x - a.x * b.y);
}

__device__ __forceinline__ float gelu_exact(float x) {
    return 0.5f * x * (1.0f + erff(x * 0.70710678118654752f));
}

// ---------------------------------------------------------------------------
// Stockham radix-2 FFT of 4096 complex points in shared memory.
// 512 threads, 12 stages, ping-pong bufA <-> bufB, result ends in bufA.
// tw[i] = exp(-2*pi*i*i/4096) for i in [0,2048). INV=true flips twiddle sign.
template <bool INV>
__device__ void fft4096(float2* bufA, float2* bufB, const float2* tw, int tid) {
    float2* src = bufA;
    float2* dst = bufB;
#pragma unroll 1
    for (int stage = 0; stage < LOGN2; ++stage) {
        __syncthreads();
        const int s = 1 << stage;
#pragma unroll
        for (int it = 0; it < 4; ++it) {
            int i = tid + it * 512;          // 0..2047  (i = p*s + q)
            int p = i >> stage;
            int q = i & (s - 1);
            float2 w = tw[p << stage];
            if (INV) w.y = -w.y;
            float2 a  = src[i];              // q + s*p == i
            float2 b  = src[i + 2048];       // q + s*(p+m)
            float2 sum = make_float2(a.x + b.x, a.y + b.y);
            float2 dif = make_float2(a.x - b.x, a.y - b.y);
            int od = q + s * 2 * p;
            dst[od]     = sum;
            dst[od + s] = cmul(dif, w);
        }
        float2* t = src; src = dst; dst = t;
    }
    __syncthreads();
}

__device__ __forceinline__ void build_twiddles(float2* tw, int tid) {
    for (int i = tid; i < 2048; i += 512) {
        float s, c;
        __sincosf(-(2.0f * PI_F / (float)N2) * (float)i, &s, &c);
        tw[i] = make_float2(c, s);
    }
}

// ---------------------------------------------------------------------------
// Kernel 1: spectrum of conv kernel k (768 rows).
// Real FFT of length 8192 (input length 4096, zero-padded) via complex 4096.
__global__ void kf_kernel(const float* __restrict__ kin) {
    extern __shared__ float2 sm[];
    float2* A  = sm;
    float2* Bb = sm + N2;
    float2* tw = sm + 2 * N2;
    const int h   = blockIdx.x;
    const int tid = threadIdx.x;

    build_twiddles(tw, tid);

    const float2* kr = (const float2*)(kin + (size_t)h * LL);
#pragma unroll
    for (int it = 0; it < 4; ++it) {
        int n = tid + it * 512;   // 0..2047 -> data
        A[n] = kr[n];
    }
#pragma unroll
    for (int it = 4; it < 8; ++it) {
        int n = tid + it * 512;   // 2048..4095 -> zero pad
        A[n] = make_float2(0.f, 0.f);
    }

    fft4096<false>(A, Bb, tw, tid);

    float2* kf = g_kf + (size_t)h * KF_STRIDE;
    for (int k = tid; k <= 2048; k += 512) {
        if (k == 0) {
            float2 Z0 = A[0];
            kf[0]    = make_float2(Z0.x + Z0.y, 0.f);   // X[0]
            kf[4096] = make_float2(Z0.x - Z0.y, 0.f);   // X[N/2]
        } else if (k == 2048) {
            float2 Z = A[2048];
            kf[2048] = make_float2(Z.x, -Z.y);          // conj(Z)
        } else {
            int kp = N2 - k;
            float2 Zk = A[k], Zp = A[kp];
            float2 Fe = make_float2(0.5f * (Zk.x + Zp.x), 0.5f * (Zk.y - Zp.y));
            float2 Fo = make_float2(0.5f * (Zk.y + Zp.y), 0.5f * (Zp.x - Zk.x));
            float sw, cw;
            __sincosf(-(2.0f * PI_F / 8192.0f) * (float)k, &sw, &cw);
            float2 W = make_float2(cw, sw);
            float2 t = cmul(Fo, W);
            kf[k]  = make_float2(Fe.x + t.x, Fe.y + t.y);        // X[k]
            kf[kp] = make_float2(Fe.x - t.x, -(Fe.y - t.y));     // conj(Fe - W*Fo)
        }
    }
}

// ---------------------------------------------------------------------------
// Kernel 2: per (b,h) row — rfft(u) * Kf -> irfft -> + D*u -> gelu -> g_y
__global__ void conv_kernel(const float* __restrict__ u, const float* __restrict__ D) {
    extern __shared__ float2 sm[];
    float2* A  = sm;
    float2* Bb = sm + N2;
    float2* tw = sm + 2 * N2;
    const int row = blockIdx.x;          // b*HH + h
    const int tid = threadIdx.x;
    const int hh  = row % HH;

    build_twiddles(tw, tid);

    const float2* u2 = (const float2*)(u + (size_t)row * LL);
    float2 ureg[4];
#pragma unroll
    for (int it = 0; it < 4; ++it) {
        int n = tid + it * 512;
        float2 v = u2[n];
        ureg[it] = v;
        A[n] = v;
    }
#pragma unroll
    for (int it = 4; it < 8; ++it) {
        int n = tid + it * 512;
        A[n] = make_float2(0.f, 0.f);
    }

    fft4096<false>(A, Bb, tw, tid);   // Z in A

    // fused: untangle (Z -> X), spectral multiply by Kf, repack (Y -> Z2), in place
    const float2* kf = g_kf + (size_t)hh * KF_STRIDE;
    for (int k = tid; k <= 2048; k += 512) {
        if (k == 0) {
            float2 Z0 = A[0];
            float X0 = Z0.x + Z0.y;      // X[0]   (real)
            float X1 = Z0.x - Z0.y;      // X[N/2] (real)
            float2 K0 = kf[0], K1 = kf[4096];
            float2 Y0 = make_float2(X0 * K0.x, X0 * K0.y);
            float2 Y1 = make_float2(X1 * K1.x, X1 * K1.y);
            float2 Ge = make_float2(0.5f * (Y0.x + Y1.x), 0.5f * (Y0.y - Y1.y));
            float2 Go = make_float2(0.5f * (Y0.x - Y1.x), 0.5f * (Y0.y + Y1.y));
            A[0] = make_float2(Ge.x - Go.y, Ge.y + Go.x);
        } else if (k == 2048) {
            float2 Z = A[2048];
            float2 X = make_float2(Z.x, -Z.y);
            float2 Y = cmul(X, kf[2048]);
            A[2048] = make_float2(Y.x, -Y.y);
        } else {
            int kp = N2 - k;
            float2 Zk = A[k], Zp = A[kp];
            float2 Fe = make_float2(0.5f * (Zk.x + Zp.x), 0.5f * (Zk.y - Zp.y));
            float2 Fo = make_float2(0.5f * (Zk.y + Zp.y), 0.5f * (Zp.x - Zk.x));
            float sw, cw;
            __sincosf(-(2.0f * PI_F / 8192.0f) * (float)k, &sw, &cw);
            float2 W = make_float2(cw, sw);
            float2 t = cmul(Fo, W);
            float2 Xk = make_float2(Fe.x + t.x, Fe.y + t.y);
            float2 Xp = make_float2(Fe.x - t.x, -(Fe.y - t.y));
            float2 Ya = cmul(Xk, kf[k]);
            float2 Yb = cmul(Xp, kf[kp]);
            float2 Ge = make_float2(0.5f * (Ya.x + Yb.x), 0.5f * (Ya.y - Yb.y));
            float2 Am = make_float2(0.5f * (Ya.x - Yb.x), 0.5f * (Ya.y + Yb.y));
            float2 Go = cmulc(Am, W);   // * exp(+2*pi*i*k/8192)
            A[k]  = make_float2(Ge.x - Go.y, Ge.y + Go.x);
            A[kp] = make_float2(Ge.x + Go.y, Go.x - Ge.y);
        }
    }

    fft4096<true>(A, Bb, tw, tid);    // z2 in A (unscaled inverse)

    const float Dh  = D[hh];
    const float inv = 1.0f / (float)N2;
    float* yout = g_y + (size_t)row * LL;
#pragma unroll
    for (int it = 0; it < 4; ++it) {
        int n = tid + it * 512;
        float2 z = A[n];
        float y0 = z.x * inv + Dh * ureg[it].x;
        float y1 = z.y * inv + Dh * ureg[it].y;
        yout[2 * n]     = gelu_exact(y0);
        yout[2 * n + 1] = gelu_exact(y1);
    }
}

// ---------------------------------------------------------------------------
// Kernel 3: per-batch GEMM  Z = W(1536x768) @ Y(768x4096), + bias, GLU fused.
// Tile: 128 W-rows (64 "a" rows h0..h0+63 paired with 64 "g" rows 768+h0..)
//       x 128 L-cols. 256 threads, 8x8 micro-tile (4 a-rows + 4 g-rows x 8 cols).
#define BKK 16
__global__ __launch_bounds__(256) void gemm_glu_kernel(
    const float* __restrict__ W, const float* __restrict__ bias,
    float* __restrict__ out) {
    __shared__ __align__(16) float Ws[BKK][128];
    __shared__ __align__(16) float Ys[BKK][128];

    const int b  = blockIdx.z;
    const int h0 = blockIdx.y * 64;
    const int l0 = blockIdx.x * 128;
    const int t  = threadIdx.x;
    const int ty = t >> 4;       // 0..15 -> 4 paired rows each
    const int tx = t & 15;       // 0..15 -> 8 cols each

    float acc_a[4][8];
    float acc_g[4][8];
#pragma unroll
    for (int j = 0; j < 4; ++j)
#pragma unroll
        for (int c = 0; c < 8; ++c) { acc_a[j][c] = 0.f; acc_g[j][c] = 0.f; }

    const float* Yb = g_y + (size_t)b * HH * LL;

    // W loader mapping: r = t & 127 (smem store conflict-free), kc = (t>>7)*8
    const int wr  = t & 127;
    const int wkc = (t >> 7) * 8;
    const int wo  = (wr < 64) ? (h0 + wr) : (HH + h0 + wr - 64);
    const float* wbase = W + (size_t)wo * HH + wkc;

    // Y loader mapping: kk = t >> 4, lc = (t&15)*8
    const int ykk = t >> 4;
    const int ylc = (t & 15) * 8;

    for (int k0 = 0; k0 < HH; k0 += BKK) {
        __syncthreads();
        {
            const float* wp = wbase + k0;
            float4 w0 = *(const float4*)wp;
            float4 w1 = *(const float4*)(wp + 4);
            Ws[wkc + 0][wr] = w0.x; Ws[wkc + 1][wr] = w0.y;
            Ws[wkc + 2][wr] = w0.z; Ws[wkc + 3][wr] = w0.w;
            Ws[wkc + 4][wr] = w1.x; Ws[wkc + 5][wr] = w1.y;
            Ws[wkc + 6][wr] = w1.z; Ws[wkc + 7][wr] = w1.w;
        }
        {
            const float* yp = Yb + (size_t)(k0 + ykk) * LL + l0 + ylc;
            float4 y0 = *(const float4*)yp;
            float4 y1 = *(const float4*)(yp + 4);
            *(float4*)&Ys[ykk][ylc]     = y0;
            *(float4*)&Ys[ykk][ylc + 4] = y1;
        }
        __syncthreads();

#pragma unroll
        for (int kk = 0; kk < BKK; ++kk) {
            float4 wa = *(const float4*)&Ws[kk][ty * 4];
            float4 wg = *(const float4*)&Ws[kk][64 + ty * 4];
            float4 y0 = *(const float4*)&Ys[kk][tx * 8];
            float4 y1 = *(const float4*)&Ys[kk][tx * 8 + 4];
            float yv[8] = {y0.x, y0.y, y0.z, y0.w, y1.x, y1.y, y1.z, y1.w};
            float wav[4] = {wa.x, wa.y, wa.z, wa.w};
            float wgv[4] = {wg.x, wg.y, wg.z, wg.w};
#pragma unroll
            for (int j = 0; j < 4; ++j)
#pragma unroll
                for (int c = 0; c < 8; ++c) {
                    acc_a[j][c] = fmaf(wav[j], yv[c], acc_a[j][c]);
                    acc_g[j][c] = fmaf(wgv[j], yv[c], acc_g[j][c]);
                }
        }
    }

    // Epilogue: GLU  out = (za) * sigmoid(zg)
#pragma unroll
    for (int j = 0; j < 4; ++j) {
        const int hrow = h0 + ty * 4 + j;
        const float ba = bias[hrow];
        const float bg = bias[HH + hrow];
        float* op = out + ((size_t)b * HH + hrow) * LL + l0 + tx * 8;
        float res[8];
#pragma unroll
        for (int c = 0; c < 8; ++c) {
            float za = acc_a[j][c] + ba;
            float zg = acc_g[j][c] + bg;
            res[c] = za / (1.0f + __expf(-zg));
        }
        *(float4*)op       = make_float4(res[0], res[1], res[2], res[3]);
        *(float4*)(op + 4) = make_float4(res[4], res[5], res[6], res[7]);
    }
}

// ---------------------------------------------------------------------------
extern "C" void kernel_launch(void* const* d_in, const int* in_sizes, int n_in,
                              void* d_out, int out_size) {
    const float* u  = (const float*)d_in[0];   // (B, H, L)
    const float* k  = (const float*)d_in[1];   // (1, H, L)
    const float* D  = (const float*)d_in[2];   // (1, H)
    const float* W  = (const float*)d_in[3];   // (2H, H)
    const float* bv = (const float*)d_in[4];   // (2H,)
    float* out = (float*)d_out;

    const int smem_fft = (N2 * 2 + 2048) * sizeof(float2);   // 80 KB
    cudaFuncSetAttribute(kf_kernel,   cudaFuncAttributeMaxDynamicSharedMemorySize, smem_fft);
    cudaFuncSetAttribute(conv_kernel, cudaFuncAttributeMaxDynamicSharedMemorySize, smem_fft);

    kf_kernel<<<HH, 512, smem_fft>>>(k);
    conv_kernel<<<BB * HH, 512, smem_fft>>>(u, D);
    gemm_glu_kernel<<<dim3(LL / 128, HH / 64, BB), 256>>>(W, bv, out);
}

// round 6
// speedup vs baseline: 1.6057x; 1.6053x over previous
#include <cuda_runtime.h>
#include <cuda_bf16.h>
#include <cstdint>

// Problem constants
#define BB 8
#define HH 768
#define LL 4096
#define N2 4096          // complex FFT size (= N/2, N = 8192)
#define LOGN2 12
#define KF_STRIDE 4100   // 4097 used, padded

#define PI_F 3.14159265358979323846f

// Scratch (device globals: allocation APIs are forbidden)
__device__ __nv_bfloat16 g_yh[(size_t)BB * HH * LL];   // gelu(y) hi, ~50 MB
__device__ __nv_bfloat16 g_yl[(size_t)BB * HH * LL];   // gelu(y) lo, ~50 MB
__device__ __nv_bfloat16 g_wh[(size_t)2 * HH * HH];    // W hi
__device__ __nv_bfloat16 g_wl[(size_t)2 * HH * HH];    // W lo
__device__ float2 g_kf[(size_t)HH * KF_STRIDE];        // kernel spectrum, ~25 MB

// ---------------------------------------------------------------------------
// complex helpers
__device__ __forceinline__ float2 cmul(float2 a, float2 b) {
    return make_float2(a.x * b.x - a.y * b.y, a.x * b.y + a.y * b.x);
}
__device__ __forceinline__ float2 cmulc(float2 a, float2 b) {  // a * conj(b)
    return make_float2(a.x * b.x + a.y * b.y, a.y * b.x - a.x * b.y);
}

__device__ __forceinline__ float gelu_exact(float x) {
    return 0.5f * x * (1.0f + erff(x * 0.70710678118654752f));
}

// ---------------------------------------------------------------------------
// Stockham radix-2 FFT of 4096 complex points in shared memory.
template <bool INV>
__device__ void fft4096(float2* bufA, float2* bufB, const float2* tw, int tid) {
    float2* src = bufA;
    float2* dst = bufB;
#pragma unroll 1
    for (int stage = 0; stage < LOGN2; ++stage) {
        __syncthreads();
        const int s = 1 << stage;
#pragma unroll
        for (int it = 0; it < 4; ++it) {
            int i = tid + it * 512;          // 0..2047  (i = p*s + q)
            int p = i >> stage;
            int q = i & (s - 1);
            float2 w = tw[p << stage];
            if (INV) w.y = -w.y;
            float2 a  = src[i];
            float2 b  = src[i + 2048];
            float2 sum = make_float2(a.x + b.x, a.y + b.y);
            float2 dif = make_float2(a.x - b.x, a.y - b.y);
            int od = q + s * 2 * p;
            dst[od]     = sum;
            dst[od + s] = cmul(dif, w);
        }
        float2* t = src; src = dst; dst = t;
    }
    __syncthreads();
}

__device__ __forceinline__ void build_twiddles(float2* tw, int tid) {
    for (int i = tid; i < 2048; i += 512) {
        float s, c;
        __sincosf(-(2.0f * PI_F / (float)N2) * (float)i, &s, &c);
        tw[i] = make_float2(c, s);
    }
}

// ---------------------------------------------------------------------------
// Kernel 1: spectrum of conv kernel k (768 rows).
__global__ void kf_kernel(const float* __restrict__ kin) {
    extern __shared__ float2 sm[];
    float2* A  = sm;
    float2* Bb = sm + N2;
    float2* tw = sm + 2 * N2;
    const int h   = blockIdx.x;
    const int tid = threadIdx.x;

    build_twiddles(tw, tid);

    const float2* kr = (const float2*)(kin + (size_t)h * LL);
#pragma unroll
    for (int it = 0; it < 4; ++it) {
        int n = tid + it * 512;
        A[n] = kr[n];
    }
#pragma unroll
    for (int it = 4; it < 8; ++it) {
        int n = tid + it * 512;
        A[n] = make_float2(0.f, 0.f);
    }

    fft4096<false>(A, Bb, tw, tid);

    float2* kf = g_kf + (size_t)h * KF_STRIDE;
    for (int k = tid; k <= 2048; k += 512) {
        if (k == 0) {
            float2 Z0 = A[0];
            kf[0]    = make_float2(Z0.x + Z0.y, 0.f);
            kf[4096] = make_float2(Z0.x - Z0.y, 0.f);
        } else if (k == 2048) {
            float2 Z = A[2048];
            kf[2048] = make_float2(Z.x, -Z.y);
        } else {
            int kp = N2 - k;
            float2 Zk = A[k], Zp = A[kp];
            float2 Fe = make_float2(0.5f * (Zk.x + Zp.x), 0.5f * (Zk.y - Zp.y));
            float2 Fo = make_float2(0.5f * (Zk.y + Zp.y), 0.5f * (Zp.x - Zk.x));
            float sw, cw;
            __sincosf(-(2.0f * PI_F / 8192.0f) * (float)k, &sw, &cw);
            float2 W = make_float2(cw, sw);
            float2 t = cmul(Fo, W);
            kf[k]  = make_float2(Fe.x + t.x, Fe.y + t.y);
            kf[kp] = make_float2(Fe.x - t.x, -(Fe.y - t.y));
        }
    }
}

// ---------------------------------------------------------------------------
// Kernel 2: per (b,h) row — rfft(u) * Kf -> irfft -> + D*u -> gelu -> split bf16
__global__ void conv_kernel(const float* __restrict__ u, const float* __restrict__ D) {
    extern __shared__ float2 sm[];
    float2* A  = sm;
    float2* Bb = sm + N2;
    float2* tw = sm + 2 * N2;
    const int row = blockIdx.x;          // b*HH + h
    const int tid = threadIdx.x;
    const int hh  = row % HH;

    build_twiddles(tw, tid);

    const float2* u2 = (const float2*)(u + (size_t)row * LL);
    float2 ureg[4];
#pragma unroll
    for (int it = 0; it < 4; ++it) {
        int n = tid + it * 512;
        float2 v = u2[n];
        ureg[it] = v;
        A[n] = v;
    }
#pragma unroll
    for (int it = 4; it < 8; ++it) {
        int n = tid + it * 512;
        A[n] = make_float2(0.f, 0.f);
    }

    fft4096<false>(A, Bb, tw, tid);   // Z in A

    const float2* kf = g_kf + (size_t)hh * KF_STRIDE;
    for (int k = tid; k <= 2048; k += 512) {
        if (k == 0) {
            float2 Z0 = A[0];
            float X0 = Z0.x + Z0.y;
            float X1 = Z0.x - Z0.y;
            float2 K0 = kf[0], K1 = kf[4096];
            float2 Y0 = make_float2(X0 * K0.x, X0 * K0.y);
            float2 Y1 = make_float2(X1 * K1.x, X1 * K1.y);
            float2 Ge = make_float2(0.5f * (Y0.x + Y1.x), 0.5f * (Y0.y - Y1.y));
            float2 Go = make_float2(0.5f * (Y0.x - Y1.x), 0.5f * (Y0.y + Y1.y));
            A[0] = make_float2(Ge.x - Go.y, Ge.y + Go.x);
        } else if (k == 2048) {
            float2 Z = A[2048];
            float2 X = make_float2(Z.x, -Z.y);
            float2 Y = cmul(X, kf[2048]);
            A[2048] = make_float2(Y.x, -Y.y);
        } else {
            int kp = N2 - k;
            float2 Zk = A[k], Zp = A[kp];
            float2 Fe = make_float2(0.5f * (Zk.x + Zp.x), 0.5f * (Zk.y - Zp.y));
            float2 Fo = make_float2(0.5f * (Zk.y + Zp.y), 0.5f * (Zp.x - Zk.x));
            float sw, cw;
            __sincosf(-(2.0f * PI_F / 8192.0f) * (float)k, &sw, &cw);
            float2 W = make_float2(cw, sw);
            float2 t = cmul(Fo, W);
            float2 Xk = make_float2(Fe.x + t.x, Fe.y + t.y);
            float2 Xp = make_float2(Fe.x - t.x, -(Fe.y - t.y));
            float2 Ya = cmul(Xk, kf[k]);
            float2 Yb = cmul(Xp, kf[kp]);
            float2 Ge = make_float2(0.5f * (Ya.x + Yb.x), 0.5f * (Ya.y - Yb.y));
            float2 Am = make_float2(0.5f * (Ya.x - Yb.x), 0.5f * (Ya.y + Yb.y));
            float2 Go = cmulc(Am, W);
            A[k]  = make_float2(Ge.x - Go.y, Ge.y + Go.x);
            A[kp] = make_float2(Ge.x + Go.y, Go.x - Ge.y);
        }
    }

    fft4096<true>(A, Bb, tw, tid);    // z2 in A (unscaled inverse)

    const float Dh  = D[hh];
    const float inv = 1.0f / (float)N2;
    __nv_bfloat16* yh = g_yh + (size_t)row * LL;
    __nv_bfloat16* yl = g_yl + (size_t)row * LL;
#pragma unroll
    for (int it = 0; it < 4; ++it) {
        int n = tid + it * 512;
        float2 z = A[n];
        float y0 = gelu_exact(z.x * inv + Dh * ureg[it].x);
        float y1 = gelu_exact(z.y * inv + Dh * ureg[it].y);
        __nv_bfloat16 h0 = __float2bfloat16(y0);
        __nv_bfloat16 h1 = __float2bfloat16(y1);
        __nv_bfloat16 l0 = __float2bfloat16(y0 - __bfloat162float(h0));
        __nv_bfloat16 l1 = __float2bfloat16(y1 - __bfloat162float(h1));
        __nv_bfloat162 hv; hv.x = h0; hv.y = h1;
        __nv_bfloat162 lv; lv.x = l0; lv.y = l1;
        *(__nv_bfloat162*)(yh + 2 * n) = hv;
        *(__nv_bfloat162*)(yl + 2 * n) = lv;
    }
}

// ---------------------------------------------------------------------------
// Kernel 2b: split W (2H x H fp32) into bf16 hi/lo
__global__ void wsplit_kernel(const float* __restrict__ W) {
    int r = blockIdx.x;
    for (int c = threadIdx.x; c < HH; c += 256) {
        float w = W[(size_t)r * HH + c];
        __nv_bfloat16 hi = __float2bfloat16(w);
        __nv_bfloat16 lo = __float2bfloat16(w - __bfloat162float(hi));
        g_wh[(size_t)r * HH + c] = hi;
        g_wl[(size_t)r * HH + c] = lo;
    }
}

// ---------------------------------------------------------------------------
// Kernel 3: tensor-core GEMM  Z = W(1536x768) @ Y(768x4096) with split-bf16
// (Wh+Wl)(Yh+Yl) ~= Wh*Yh + Wh*Yl + Wl*Yh  (fp32 accum), bias + GLU fused.
// CTA: 128 M-rows (64 'a' + 64 'g') x 128 N-cols, K chunks of 32.
// 8 warps = 2 (m) x 4 (n); warp tile: (32a+32g) x 32.
__device__ __forceinline__ void mma_bf16(float* c, const uint32_t* a, const uint32_t* b) {
    asm volatile(
        "mma.sync.aligned.m16n8k16.row.col.f32.bf16.bf16.f32 "
        "{%0,%1,%2,%3}, {%4,%5,%6,%7}, {%8,%9}, {%0,%1,%2,%3};"
        : "+f"(c[0]), "+f"(c[1]), "+f"(c[2]), "+f"(c[3])
        : "r"(a[0]), "r"(a[1]), "r"(a[2]), "r"(a[3]), "r"(b[0]), "r"(b[1]));
}

#define WS_STRIDE 40      // halves per row (20 words): bank-conflict-free A frags
#define YS_STRIDE 136     // words per pair-row: bank-conflict-free B frags

__global__ __launch_bounds__(256) void gemm_glu_kernel(
    const float* __restrict__ bias, float* __restrict__ out) {
    __shared__ __nv_bfloat16 Whs[128][WS_STRIDE];
    __shared__ __nv_bfloat16 Wls[128][WS_STRIDE];
    __shared__ uint32_t Yph[16][YS_STRIDE];   // {Y[2p][n], Y[2p+1][n]} packed
    __shared__ uint32_t Ypl[16][YS_STRIDE];

    const int b  = blockIdx.z;
    const int h0 = blockIdx.y * 64;
    const int l0 = blockIdx.x * 128;
    const int t  = threadIdx.x;
    const int wid  = t >> 5;
    const int lane = t & 31;
    const int wm = wid >> 2;          // 0..1
    const int wn = wid & 3;           // 0..3
    const int g  = lane >> 2;         // 0..7
    const int tq = lane & 3;          // 0..3

    float acc[4][4][4];               // [mfrag: 2a+2g][nfrag][4]
#pragma unroll
    for (int f = 0; f < 4; ++f)
#pragma unroll
        for (int j = 0; j < 4; ++j)
#pragma unroll
            for (int r = 0; r < 4; ++r) acc[f][j][r] = 0.f;

    // loader mappings
    const int wr  = t >> 1;                 // 0..127 tile m-row
    const int seg = t & 1;                  // 0/1 -> 16-half segment
    const int wrow = (wr < 64) ? (h0 + wr) : (HH + h0 + wr - 64);
    const __nv_bfloat16* whp = g_wh + (size_t)wrow * HH + 16 * seg;
    const __nv_bfloat16* wlp = g_wl + (size_t)wrow * HH + 16 * seg;

    const int pr = t >> 4;                  // 0..15 pair-row
    const int lc = (t & 15) * 8;            // 0..120
    const __nv_bfloat16* ybh = g_yh + (size_t)b * HH * LL + (size_t)l0 + lc;
    const __nv_bfloat16* ybl = g_yl + (size_t)b * HH * LL + (size_t)l0 + lc;

    const uint32_t* WhW = (const uint32_t*)&Whs[0][0];
    const uint32_t* WlW = (const uint32_t*)&Wls[0][0];

    const int m0s[4] = {wm * 32, wm * 32 + 16, 64 + wm * 32, 64 + wm * 32 + 16};

    for (int k0 = 0; k0 < HH; k0 += 32) {
        __syncthreads();
        // W tiles: 128 rows x 32 halves (hi, lo). Each (wr,seg) thread loads
        // 16 halves = 2 x uint4.  (R5 bug: only 8 halves were loaded.)
        *(uint4*)&Whs[wr][16 * seg]     = *(const uint4*)(whp + k0);
        *(uint4*)&Whs[wr][16 * seg + 8] = *(const uint4*)(whp + k0 + 8);
        *(uint4*)&Wls[wr][16 * seg]     = *(const uint4*)(wlp + k0);
        *(uint4*)&Wls[wr][16 * seg + 8] = *(const uint4*)(wlp + k0 + 8);
        // Y tiles: interleave k-pairs
        {
            const size_t re = (size_t)(k0 + 2 * pr) * LL;
            const size_t ro = re + LL;
            uint4 e = *(const uint4*)(ybh + re);
            uint4 o = *(const uint4*)(ybh + ro);
            *(uint4*)&Yph[pr][lc] = make_uint4(
                __byte_perm(e.x, o.x, 0x5410), __byte_perm(e.x, o.x, 0x7632),
                __byte_perm(e.y, o.y, 0x5410), __byte_perm(e.y, o.y, 0x7632));
            *(uint4*)&Yph[pr][lc + 4] = make_uint4(
                __byte_perm(e.z, o.z, 0x5410), __byte_perm(e.z, o.z, 0x7632),
                __byte_perm(e.w, o.w, 0x5410), __byte_perm(e.w, o.w, 0x7632));
            uint4 el = *(const uint4*)(ybl + re);
            uint4 ol = *(const uint4*)(ybl + ro);
            *(uint4*)&Ypl[pr][lc] = make_uint4(
                __byte_perm(el.x, ol.x, 0x5410), __byte_perm(el.x, ol.x, 0x7632),
                __byte_perm(el.y, ol.y, 0x5410), __byte_perm(el.y, ol.y, 0x7632));
            *(uint4*)&Ypl[pr][lc + 4] = make_uint4(
                __byte_perm(el.z, ol.z, 0x5410), __byte_perm(el.z, ol.z, 0x7632),
                __byte_perm(el.w, ol.w, 0x5410), __byte_perm(el.w, ol.w, 0x7632));
        }
        __syncthreads();

#pragma unroll
        for (int ks = 0; ks < 2; ++ks) {
            const int wcol = ks * 8 + tq;        // word col within 20-word row
            const int prb  = ks * 8 + tq;        // pair-row base for B
            uint32_t AH[4][4], AL[4][4], BH[4][2], BL[4][2];
#pragma unroll
            for (int f = 0; f < 4; ++f) {
                int r0 = (m0s[f] + g) * (WS_STRIDE / 2) + wcol;
                int r1 = (m0s[f] + g + 8) * (WS_STRIDE / 2) + wcol;
                AH[f][0] = WhW[r0];     AH[f][1] = WhW[r1];
                AH[f][2] = WhW[r0 + 4]; AH[f][3] = WhW[r1 + 4];
                AL[f][0] = WlW[r0];     AL[f][1] = WlW[r1];
                AL[f][2] = WlW[r0 + 4]; AL[f][3] = WlW[r1 + 4];
            }
#pragma unroll
            for (int j = 0; j < 4; ++j) {
                int n = wn * 32 + j * 8 + g;
                BH[j][0] = Yph[prb][n];     BH[j][1] = Yph[prb + 4][n];
                BL[j][0] = Ypl[prb][n];     BL[j][1] = Ypl[prb + 4][n];
            }
#pragma unroll
            for (int f = 0; f < 4; ++f)
#pragma unroll
                for (int j = 0; j < 4; ++j) {
                    mma_bf16(acc[f][j], AH[f], BH[j]);
                    mma_bf16(acc[f][j], AH[f], BL[j]);
                    mma_bf16(acc[f][j], AL[f], BH[j]);
                }
        }
    }

    // Epilogue: GLU.  a-frag f pairs with g-frag f+2 (same rows).
#pragma unroll
    for (int ai = 0; ai < 2; ++ai) {
        const int hrow0 = h0 + wm * 32 + ai * 16 + g;     // rows (c0,c1)
        const int hrow8 = hrow0 + 8;                       // rows (c2,c3)
        const float ba0 = bias[hrow0],      ba8 = bias[hrow8];
        const float bg0 = bias[HH + hrow0], bg8 = bias[HH + hrow8];
        float* o0 = out + ((size_t)b * HH + hrow0) * LL + l0 + wn * 32;
        float* o8 = out + ((size_t)b * HH + hrow8) * LL + l0 + wn * 32;
#pragma unroll
        for (int j = 0; j < 4; ++j) {
            const int cc = j * 8 + 2 * tq;
            float za0 = acc[ai][j][0] + ba0, za1 = acc[ai][j][1] + ba0;
            float zg0 = acc[ai + 2][j][0] + bg0, zg1 = acc[ai + 2][j][1] + bg0;
            float za2 = acc[ai][j][2] + ba8, za3 = acc[ai][j][3] + ba8;
            float zg2 = acc[ai + 2][j][2] + bg8, zg3 = acc[ai + 2][j][3] + bg8;
            *(float2*)(o0 + cc) = make_float2(za0 / (1.0f + __expf(-zg0)),
                                              za1 / (1.0f + __expf(-zg1)));
            *(float2*)(o8 + cc) = make_float2(za2 / (1.0f + __expf(-zg2)),
                                              za3 / (1.0f + __expf(-zg3)));
        }
    }
}

// ---------------------------------------------------------------------------
extern "C" void kernel_launch(void* const* d_in, const int* in_sizes, int n_in,
                              void* d_out, int out_size) {
    const float* u  = (const float*)d_in[0];   // (B, H, L)
    const float* k  = (const float*)d_in[1];   // (1, H, L)
    const float* D  = (const float*)d_in[2];   // (1, H)
    const float* W  = (const float*)d_in[3];   // (2H, H)
    const float* bv = (const float*)d_in[4];   // (2H,)
    float* out = (float*)d_out;

    const int smem_fft = (N2 * 2 + 2048) * sizeof(float2);   // 80 KB
    cudaFuncSetAttribute(kf_kernel,   cudaFuncAttributeMaxDynamicSharedMemorySize, smem_fft);
    cudaFuncSetAttribute(conv_kernel, cudaFuncAttributeMaxDynamicSharedMemorySize, smem_fft);

    kf_kernel<<<HH, 512, smem_fft>>>(k);
    wsplit_kernel<<<2 * HH, 256>>>(W);
    conv_kernel<<<BB * HH, 512, smem_fft>>>(u, D);
    gemm_glu_kernel<<<dim3(LL / 128, HH / 64, BB), 256>>>(bv, out);
}

// round 8
// speedup vs baseline: 1.9099x; 1.1895x over previous
#include <cuda_runtime.h>
#include <cuda_bf16.h>
#include <cstdint>

// Problem constants
#define BB 8
#define HH 768
#define LL 4096
#define N2 4096          // complex FFT size (= N/2, N = 8192)
#define LOGN2 12
#define KF_STRIDE 4100   // 4097 used, padded

#define PI_F 3.14159265358979323846f

// Scratch (device globals: allocation APIs are forbidden)
__device__ __nv_bfloat16 g_yh[(size_t)BB * HH * LL];   // gelu(y) hi, ~50 MB
__device__ __nv_bfloat16 g_yl[(size_t)BB * HH * LL];   // gelu(y) lo, ~50 MB
__device__ __nv_bfloat16 g_wh[(size_t)2 * HH * HH];    // W hi
__device__ __nv_bfloat16 g_wl[(size_t)2 * HH * HH];    // W lo
__device__ float2 g_kf[(size_t)HH * KF_STRIDE];        // kernel spectrum, ~25 MB

// ---------------------------------------------------------------------------
// complex helpers
__device__ __forceinline__ float2 cmul(float2 a, float2 b) {
    return make_float2(a.x * b.x - a.y * b.y, a.x * b.y + a.y * b.x);
}
__device__ __forceinline__ float2 cmulc(float2 a, float2 b) {  // a * conj(b)
    return make_float2(a.x * b.x + a.y * b.y, a.y * b.x - a.x * b.y);
}

__device__ __forceinline__ float gelu_exact(float x) {
    return 0.5f * x * (1.0f + erff(x * 0.70710678118654752f));
}

// ---------------------------------------------------------------------------
// Stockham radix-2 FFT of 4096 complex points in shared memory.
template <bool INV>
__device__ void fft4096(float2* bufA, float2* bufB, const float2* tw, int tid) {
    float2* src = bufA;
    float2* dst = bufB;
#pragma unroll 1
    for (int stage = 0; stage < LOGN2; ++stage) {
        __syncthreads();
        const int s = 1 << stage;
#pragma unroll
        for (int it = 0; it < 4; ++it) {
            int i = tid + it * 512;          // 0..2047  (i = p*s + q)
            int p = i >> stage;
            int q = i & (s - 1);
            float2 w = tw[p << stage];
            if (INV) w.y = -w.y;
            float2 a  = src[i];
            float2 b  = src[i + 2048];
            float2 sum = make_float2(a.x + b.x, a.y + b.y);
            float2 dif = make_float2(a.x - b.x, a.y - b.y);
            int od = q + s * 2 * p;
            dst[od]     = sum;
            dst[od + s] = cmul(dif, w);
        }
        float2* t = src; src = dst; dst = t;
    }
    __syncthreads();
}

__device__ __forceinline__ void build_twiddles(float2* tw, int tid) {
    for (int i = tid; i < 2048; i += 512) {
        float s, c;
        __sincosf(-(2.0f * PI_F / (float)N2) * (float)i, &s, &c);
        tw[i] = make_float2(c, s);
    }
}

// ---------------------------------------------------------------------------
// Kernel 1: spectrum of conv kernel k (768 rows).
__global__ void kf_kernel(const float* __restrict__ kin) {
    extern __shared__ float2 sm[];
    float2* A  = sm;
    float2* Bb = sm + N2;
    float2* tw = sm + 2 * N2;
    const int h   = blockIdx.x;
    const int tid = threadIdx.x;

    build_twiddles(tw, tid);

    const float2* kr = (const float2*)(kin + (size_t)h * LL);
#pragma unroll
    for (int it = 0; it < 4; ++it) {
        int n = tid + it * 512;
        A[n] = kr[n];
    }
#pragma unroll
    for (int it = 4; it < 8; ++it) {
        int n = tid + it * 512;
        A[n] = make_float2(0.f, 0.f);
    }

    fft4096<false>(A, Bb, tw, tid);

    float2* kf = g_kf + (size_t)h * KF_STRIDE;
    for (int k = tid; k <= 2048; k += 512) {
        if (k == 0) {
            float2 Z0 = A[0];
            kf[0]    = make_float2(Z0.x + Z0.y, 0.f);
            kf[4096] = make_float2(Z0.x - Z0.y, 0.f);
        } else if (k == 2048) {
            float2 Z = A[2048];
            kf[2048] = make_float2(Z.x, -Z.y);
        } else {
            int kp = N2 - k;
            float2 Zk = A[k], Zp = A[kp];
            float2 Fe = make_float2(0.5f * (Zk.x + Zp.x), 0.5f * (Zk.y - Zp.y));
            float2 Fo = make_float2(0.5f * (Zk.y + Zp.y), 0.5f * (Zp.x - Zk.x));
            float sw, cw;
            __sincosf(-(2.0f * PI_F / 8192.0f) * (float)k, &sw, &cw);
            float2 W = make_float2(cw, sw);
            float2 t = cmul(Fo, W);
            kf[k]  = make_float2(Fe.x + t.x, Fe.y + t.y);
            kf[kp] = make_float2(Fe.x - t.x, -(Fe.y - t.y));
        }
    }
}

// ---------------------------------------------------------------------------
// Kernel 2: per (b,h) row — rfft(u) * Kf -> irfft -> + D*u -> gelu -> split bf16
__global__ void conv_kernel(const float* __restrict__ u, const float* __restrict__ D) {
    extern __shared__ float2 sm[];
    float2* A  = sm;
    float2* Bb = sm + N2;
    float2* tw = sm + 2 * N2;
    const int row = blockIdx.x;          // b*HH + h
    const int tid = threadIdx.x;
    const int hh  = row % HH;

    build_twiddles(tw, tid);

    const float2* u2 = (const float2*)(u + (size_t)row * LL);
    float2 ureg[4];
#pragma unroll
    for (int it = 0; it < 4; ++it) {
        int n = tid + it * 512;
        float2 v = u2[n];
        ureg[it] = v;
        A[n] = v;
    }
#pragma unroll
    for (int it = 4; it < 8; ++it) {
        int n = tid + it * 512;
        A[n] = make_float2(0.f, 0.f);
    }

    fft4096<false>(A, Bb, tw, tid);   // Z in A

    const float2* kf = g_kf + (size_t)hh * KF_STRIDE;
    for (int k = tid; k <= 2048; k += 512) {
        if (k == 0) {
            float2 Z0 = A[0];
            float X0 = Z0.x + Z0.y;
            float X1 = Z0.x - Z0.y;
            float2 K0 = kf[0], K1 = kf[4096];
            float2 Y0 = make_float2(X0 * K0.x, X0 * K0.y);
            float2 Y1 = make_float2(X1 * K1.x, X1 * K1.y);
            float2 Ge = make_float2(0.5f * (Y0.x + Y1.x), 0.5f * (Y0.y - Y1.y));
            float2 Go = make_float2(0.5f * (Y0.x - Y1.x), 0.5f * (Y0.y + Y1.y));
            A[0] = make_float2(Ge.x - Go.y, Ge.y + Go.x);
        } else if (k == 2048) {
            float2 Z = A[2048];
            float2 X = make_float2(Z.x, -Z.y);
            float2 Y = cmul(X, kf[2048]);
            A[2048] = make_float2(Y.x, -Y.y);
        } else {
            int kp = N2 - k;
            float2 Zk = A[k], Zp = A[kp];
            float2 Fe = make_float2(0.5f * (Zk.x + Zp.x), 0.5f * (Zk.y - Zp.y));
            float2 Fo = make_float2(0.5f * (Zk.y + Zp.y), 0.5f * (Zp.x - Zk.x));
            float sw, cw;
            __sincosf(-(2.0f * PI_F / 8192.0f) * (float)k, &sw, &cw);
            float2 W = make_float2(cw, sw);
            float2 t = cmul(Fo, W);
            float2 Xk = make_float2(Fe.x + t.x, Fe.y + t.y);
            float2 Xp = make_float2(Fe.x - t.x, -(Fe.y - t.y));
            float2 Ya = cmul(Xk, kf[k]);
            float2 Yb = cmul(Xp, kf[kp]);
            float2 Ge = make_float2(0.5f * (Ya.x + Yb.x), 0.5f * (Ya.y - Yb.y));
            float2 Am = make_float2(0.5f * (Ya.x - Yb.x), 0.5f * (Ya.y + Yb.y));
            float2 Go = cmulc(Am, W);
            A[k]  = make_float2(Ge.x - Go.y, Ge.y + Go.x);
            A[kp] = make_float2(Ge.x + Go.y, Go.x - Ge.y);
        }
    }

    fft4096<true>(A, Bb, tw, tid);    // z2 in A (unscaled inverse)

    const float Dh  = D[hh];
    const float inv = 1.0f / (float)N2;
    __nv_bfloat16* yh = g_yh + (size_t)row * LL;
    __nv_bfloat16* yl = g_yl + (size_t)row * LL;
#pragma unroll
    for (int it = 0; it < 4; ++it) {
        int n = tid + it * 512;
        float2 z = A[n];
        float y0 = gelu_exact(z.x * inv + Dh * ureg[it].x);
        float y1 = gelu_exact(z.y * inv + Dh * ureg[it].y);
        __nv_bfloat16 h0 = __float2bfloat16(y0);
        __nv_bfloat16 h1 = __float2bfloat16(y1);
        __nv_bfloat16 l0 = __float2bfloat16(y0 - __bfloat162float(h0));
        __nv_bfloat16 l1 = __float2bfloat16(y1 - __bfloat162float(h1));
        __nv_bfloat162 hv; hv.x = h0; hv.y = h1;
        __nv_bfloat162 lv; lv.x = l0; lv.y = l1;
        *(__nv_bfloat162*)(yh + 2 * n) = hv;
        *(__nv_bfloat162*)(yl + 2 * n) = lv;
    }
}

// ---------------------------------------------------------------------------
// Kernel 2b: split W (2H x H fp32) into bf16 hi/lo
__global__ void wsplit_kernel(const float* __restrict__ W) {
    int r = blockIdx.x;
    for (int c = threadIdx.x; c < HH; c += 256) {
        float w = W[(size_t)r * HH + c];
        __nv_bfloat16 hi = __float2bfloat16(w);
        __nv_bfloat16 lo = __float2bfloat16(w - __bfloat162float(hi));
        g_wh[(size_t)r * HH + c] = hi;
        g_wl[(size_t)r * HH + c] = lo;
    }
}

// ---------------------------------------------------------------------------
// Kernel 3: tensor-core GEMM  Z = W(1536x768) @ Y(768x4096) with split-bf16
// (Wh+Wl)(Yh+Yl) ~= Wh*Yh + Wh*Yl + Wl*Yh  (fp32 accum), bias + GLU fused.
// CTA: 128 M-rows (64 'a' + 64 'g') x 128 N-cols, K chunks of 32.
// 8 warps = 2 (m) x 4 (n); warp tile: (32a+32g) x 32.
// R7: __launch_bounds__(256,2) for 2 CTAs/SM; W tiles via cp.async.
__device__ __forceinline__ void mma_bf16(float* c, const uint32_t* a, const uint32_t* b) {
    asm volatile(
        "mma.sync.aligned.m16n8k16.row.col.f32.bf16.bf16.f32 "
        "{%0,%1,%2,%3}, {%4,%5,%6,%7}, {%8,%9}, {%0,%1,%2,%3};"
        : "+f"(c[0]), "+f"(c[1]), "+f"(c[2]), "+f"(c[3])
        : "r"(a[0]), "r"(a[1]), "r"(a[2]), "r"(a[3]), "r"(b[0]), "r"(b[1]));
}

__device__ __forceinline__ void cp_async16(void* smem_dst, const void* gmem_src) {
    uint32_t s = (uint32_t)__cvta_generic_to_shared(smem_dst);
    asm volatile("cp.async.ca.shared.global [%0], [%1], 16;\n" :: "r"(s), "l"(gmem_src));
}
__device__ __forceinline__ void cp_async_commit() {
    asm volatile("cp.async.commit_group;\n" ::: "memory");
}
__device__ __forceinline__ void cp_async_wait_all() {
    asm volatile("cp.async.wait_group 0;\n" ::: "memory");
}

#define WS_STRIDE 40      // halves per row (20 words): bank-conflict-free A frags
#define YS_STRIDE 136     // words per pair-row: bank-conflict-free B frags

__global__ __launch_bounds__(256, 2) void gemm_glu_kernel(
    const float* __restrict__ bias, float* __restrict__ out) {
    __shared__ __nv_bfloat16 Whs[128][WS_STRIDE];
    __shared__ __nv_bfloat16 Wls[128][WS_STRIDE];
    __shared__ uint32_t Yph[16][YS_STRIDE];   // {Y[2p][n], Y[2p+1][n]} packed
    __shared__ uint32_t Ypl[16][YS_STRIDE];

    const int b  = blockIdx.z;
    const int h0 = blockIdx.y * 64;
    const int l0 = blockIdx.x * 128;
    const int t  = threadIdx.x;
    const int wid  = t >> 5;
    const int lane = t & 31;
    const int wm = wid >> 2;          // 0..1
    const int wn = wid & 3;           // 0..3
    const int g  = lane >> 2;         // 0..7
    const int tq = lane & 3;          // 0..3

    float acc[4][4][4];               // [mfrag: 2a+2g][nfrag][4]
#pragma unroll
    for (int f = 0; f < 4; ++f)
#pragma unroll
        for (int j = 0; j < 4; ++j)
#pragma unroll
            for (int r = 0; r < 4; ++r) acc[f][j][r] = 0.f;

    // loader mappings
    const int wr  = t >> 1;                 // 0..127 tile m-row
    const int seg = t & 1;                  // 0/1 -> 16-half segment
    const int wrow = (wr < 64) ? (h0 + wr) : (HH + h0 + wr - 64);
    const __nv_bfloat16* whp = g_wh + (size_t)wrow * HH + 16 * seg;
    const __nv_bfloat16* wlp = g_wl + (size_t)wrow * HH + 16 * seg;

    const int pr = t >> 4;                  // 0..15 pair-row
    const int lc = (t & 15) * 8;            // 0..120
    const __nv_bfloat16* ybh = g_yh + (size_t)b * HH * LL + (size_t)l0 + lc;
    const __nv_bfloat16* ybl = g_yl + (size_t)b * HH * LL + (size_t)l0 + lc;

    const uint32_t* WhW = (const uint32_t*)&Whs[0][0];
    const uint32_t* WlW = (const uint32_t*)&Wls[0][0];

    const int m0s[4] = {wm * 32, wm * 32 + 16, 64 + wm * 32, 64 + wm * 32 + 16};

    for (int k0 = 0; k0 < HH; k0 += 32) {
        __syncthreads();
        // W tiles via cp.async: 16 halves = 2 x 16B per (wr,seg) thread, x hi/lo.
        cp_async16(&Whs[wr][16 * seg],     whp + k0);
        cp_async16(&Whs[wr][16 * seg + 8], whp + k0 + 8);
        cp_async16(&Wls[wr][16 * seg],     wlp + k0);
        cp_async16(&Wls[wr][16 * seg + 8], wlp + k0 + 8);
        cp_async_commit();
        // Y tiles: LDG + k-pair interleave + STS (overlaps with W cp.async)
        {
            const size_t re = (size_t)(k0 + 2 * pr) * LL;
            const size_t ro = re + LL;
            uint4 e = *(const uint4*)(ybh + re);
            uint4 o = *(const uint4*)(ybh + ro);
            *(uint4*)&Yph[pr][lc] = make_uint4(
                __byte_perm(e.x, o.x, 0x5410), __byte_perm(e.x, o.x, 0x7632),
                __byte_perm(e.y, o.y, 0x5410), __byte_perm(e.y, o.y, 0x7632));
            *(uint4*)&Yph[pr][lc + 4] = make_uint4(
                __byte_perm(e.z, o.z, 0x5410), __byte_perm(e.z, o.z, 0x7632),
                __byte_perm(e.w, o.w, 0x5410), __byte_perm(e.w, o.w, 0x7632));
            uint4 el = *(const uint4*)(ybl + re);
            uint4 ol = *(const uint4*)(ybl + ro);
            *(uint4*)&Ypl[pr][lc] = make_uint4(
                __byte_perm(el.x, ol.x, 0x5410), __byte_perm(el.x, ol.x, 0x7632),
                __byte_perm(el.y, ol.y, 0x5410), __byte_perm(el.y, ol.y, 0x7632));
            *(uint4*)&Ypl[pr][lc + 4] = make_uint4(
                __byte_perm(el.z, ol.z, 0x5410), __byte_perm(el.z, ol.z, 0x7632),
                __byte_perm(el.w, ol.w, 0x5410), __byte_perm(el.w, ol.w, 0x7632));
        }
        cp_async_wait_all();
        __syncthreads();

#pragma unroll
        for (int ks = 0; ks < 2; ++ks) {
            const int wcol = ks * 8 + tq;        // word col within 20-word row
            const int prb  = ks * 8 + tq;        // pair-row base for B
            uint32_t AH[4][4], AL[4][4], BH[4][2], BL[4][2];
#pragma unroll
            for (int f = 0; f < 4; ++f) {
                int r0 = (m0s[f] + g) * (WS_STRIDE / 2) + wcol;
                int r1 = (m0s[f] + g + 8) * (WS_STRIDE / 2) + wcol;
                AH[f][0] = WhW[r0];     AH[f][1] = WhW[r1];
                AH[f][2] = WhW[r0 + 4]; AH[f][3] = WhW[r1 + 4];
                AL[f][0] = WlW[r0];     AL[f][1] = WlW[r1];
                AL[f][2] = WlW[r0 + 4]; AL[f][3] = WlW[r1 + 4];
            }
#pragma unroll
            for (int j = 0; j < 4; ++j) {
                int n = wn * 32 + j * 8 + g;
                BH[j][0] = Yph[prb][n];     BH[j][1] = Yph[prb + 4][n];
                BL[j][0] = Ypl[prb][n];     BL[j][1] = Ypl[prb + 4][n];
            }
#pragma unroll
            for (int f = 0; f < 4; ++f)
#pragma unroll
                for (int j = 0; j < 4; ++j) {
                    mma_bf16(acc[f][j], AH[f], BH[j]);
                    mma_bf16(acc[f][j], AH[f], BL[j]);
                    mma_bf16(acc[f][j], AL[f], BH[j]);
                }
        }
    }

    // Epilogue: GLU.  a-frag f pairs with g-frag f+2 (same rows).
#pragma unroll
    for (int ai = 0; ai < 2; ++ai) {
        const int hrow0 = h0 + wm * 32 + ai * 16 + g;     // rows (c0,c1)
        const int hrow8 = hrow0 + 8;                       // rows (c2,c3)
        const float ba0 = bias[hrow0],      ba8 = bias[hrow8];
        const float bg0 = bias[HH + hrow0], bg8 = bias[HH + hrow8];
        float* o0 = out + ((size_t)b * HH + hrow0) * LL + l0 + wn * 32;
        float* o8 = out + ((size_t)b * HH + hrow8) * LL + l0 + wn * 32;
#pragma unroll
        for (int j = 0; j < 4; ++j) {
            const int cc = j * 8 + 2 * tq;
            float za0 = acc[ai][j][0] + ba0, za1 = acc[ai][j][1] + ba0;
            float zg0 = acc[ai + 2][j][0] + bg0, zg1 = acc[ai + 2][j][1] + bg0;
            float za2 = acc[ai][j][2] + ba8, za3 = acc[ai][j][3] + ba8;
            float zg2 = acc[ai + 2][j][2] + bg8, zg3 = acc[ai + 2][j][3] + bg8;
            *(float2*)(o0 + cc) = make_float2(za0 / (1.0f + __expf(-zg0)),
                                              za1 / (1.0f + __expf(-zg1)));
            *(float2*)(o8 + cc) = make_float2(za2 / (1.0f + __expf(-zg2)),
                                              za3 / (1.0f + __expf(-zg3)));
        }
    }
}

// ---------------------------------------------------------------------------
extern "C" void kernel_launch(void* const* d_in, const int* in_sizes, int n_in,
                              void* d_out, int out_size) {
    const float* u  = (const float*)d_in[0];   // (B, H, L)
    const float* k  = (const float*)d_in[1];   // (1, H, L)
    const float* D  = (const float*)d_in[2];   // (1, H)
    const float* W  = (const float*)d_in[3];   // (2H, H)
    const float* bv = (const float*)d_in[4];   // (2H,)
    float* out = (float*)d_out;

    const int smem_fft = (N2 * 2 + 2048) * sizeof(float2);   // 80 KB
    cudaFuncSetAttribute(kf_kernel,   cudaFuncAttributeMaxDynamicSharedMemorySize, smem_fft);
    cudaFuncSetAttribute(conv_kernel, cudaFuncAttributeMaxDynamicSharedMemorySize, smem_fft);

    kf_kernel<<<HH, 512, smem_fft>>>(k);
    wsplit_kernel<<<2 * HH, 256>>>(W);
    conv_kernel<<<BB * HH, 512, smem_fft>>>(u, D);
    gemm_glu_kernel<<<dim3(LL / 128, HH / 64, BB), 256>>>(bv, out);
}